// round 15
// baseline (speedup 1.0000x reference)
#include <cuda_runtime.h>
#include <cuda_fp16.h>
#include <math.h>
#include <stdint.h>

// Problem constants
#define B    8
#define HH   128
#define WW   128
#define NP   16384        // H*W
#define D    27           // PATCH*PATCH*C
#define DP   28           // padded
#define NA   128          // number of anchors
#define AG   32           // anchors per CTA
#define NG   (NA / AG)    // 4 anchor groups
#define PC   32           // p-chunks
#define PCHUNK (NP / PC)  // 512 pixels per chunk (4 image rows)
#define TPB  256
#define LOG2E 1.4426950408889634f

// Scratch (device globals)
__device__ __align__(16) float g_sumPart[B * NA * PC];
__device__ float g_pos  [B * NA];
__device__ float g_in121[B * NA];
__device__ float g_cross[B * NA];
__device__ int   g_cnt  [NA * 3];

__device__ __forceinline__ float ex2_approx(float x) {
    float y;
    asm("ex2.approx.f32 %0, %1;" : "=f"(y) : "f"(x));
    return y;
}

__device__ __forceinline__ int iclamp(int v, int lo, int hi) {
    return min(max(v, lo), hi);
}

// Build normalized patch (fp32) by gathering 3x3 neighborhood from GLOBAL latents.
__device__ __forceinline__ void build_patch_global(
    const float* __restrict__ lat, int b, int y, int x, float* v)
{
    float ss = 0.0f;
    int d = 0;
#pragma unroll
    for (int dy = -1; dy <= 1; dy++) {
        int yy = iclamp(y + dy, 0, HH - 1);
#pragma unroll
        for (int dx = -1; dx <= 1; dx++) {
            int xx = iclamp(x + dx, 0, WW - 1);
            const float* s = lat + (((size_t)(b * HH + yy) * WW + xx) * 3);
            float a0 = s[0], a1 = s[1], a2 = s[2];
            v[d] = a0; v[d + 1] = a1; v[d + 2] = a2;
            ss += a0 * a0 + a1 * a1 + a2 * a2;
            d += 3;
        }
    }
    float inv = 1.0f / fmaxf(sqrtf(ss), 1e-12f);
#pragma unroll
    for (int k = 0; k < D; k++) v[k] *= inv;
    v[D] = 0.0f;
}

__device__ __forceinline__ float dot27(const float* a, const float* c) {
    float dot = 0.0f;
#pragma unroll
    for (int k = 0; k < D; k++) dot = fmaf(a[k], c[k], dot);
    return dot;
}

// ---------------------------------------------------------------------------
// Kernel 1: fused patches + HFMA2 exp-sums + window/cross terms.
// grid (PC, NG, B), block 256, 2 CTAs/SM.
// ---------------------------------------------------------------------------
__global__ void __launch_bounds__(TPB, 2)
mega_kernel(const float* __restrict__ lat, const int* __restrict__ aidx)
{
    int pc = blockIdx.x;       // chunk 0..31 (4 image rows each)
    int ng = blockIdx.y;       // anchor quad 0..3
    int b  = blockIdx.z;
    int tid = threadIdx.x;
    int wid = tid >> 5, lane = tid & 31;

    __shared__ float sRows[6 * WW * 3];          // 2304 floats; reused as window region
    __shared__ unsigned int sA[AG * DP];         // dup half2 anchors (x log2e)
    __shared__ float rS[AG][TPB / 32];

    // ---- Stage latent rows pc*4-1 .. pc*4+4 (row-clamped), coalesced ----
    int r0m1 = pc * 4 - 1;
    for (int t = tid; t < 6 * WW * 3; t += TPB) {
        int s = t / (WW * 3);
        int j = t - s * (WW * 3);
        int gr = iclamp(r0m1 + s, 0, HH - 1);
        sRows[t] = lat[((size_t)(b * HH + gr) * WW) * 3 + j];
    }

    // ---- Stage anchors (32 threads, one anchor each) ----
    if (tid < AG) {
        int ai = aidx[ng * AG + tid];
        float v[DP];
        build_patch_global(lat, b, ai >> 7, ai & 127, v);
#pragma unroll
        for (int k = 0; k < DP; k++) {
            __half2 hh = __half2half2(__float2half(v[k] * LOG2E));
            sA[tid * DP + k] = *reinterpret_cast<unsigned int*>(&hh);
        }
    }
    __syncthreads();

    // ---- Build this thread's 2 pixel patches from sRows, pack half2 ----
    unsigned int vv[DP];   // half2(px0_d, px1_d)
    {
        int p0 = pc * PCHUNK + 2 * tid;
#pragma unroll
        for (int px = 0; px < 2; px++) {
            int p = p0 + px;
            int y = p >> 7, x = p & 127;
            float v[DP];
            float ss = 0.0f;
            int d = 0;
#pragma unroll
            for (int dy = -1; dy <= 1; dy++) {
                int ys = iclamp(y + dy, 0, HH - 1) - r0m1;   // slot in sRows
#pragma unroll
                for (int dx = -1; dx <= 1; dx++) {
                    int xs = iclamp(x + dx, 0, WW - 1);
                    const float* s = &sRows[(ys * WW + xs) * 3];
                    float a0 = s[0], a1 = s[1], a2 = s[2];
                    v[d] = a0; v[d + 1] = a1; v[d + 2] = a2;
                    ss += a0 * a0 + a1 * a1 + a2 * a2;
                    d += 3;
                }
            }
            float inv = 1.0f / fmaxf(sqrtf(ss), 1e-12f);
#pragma unroll
            for (int k = 0; k < DP; k++) {
                unsigned short h = __half_as_ushort(
                    __float2half(k < D ? v[k] * inv : 0.0f));
                if (px == 0) vv[k] = h;
                else         vv[k] |= ((unsigned int)h << 16);
            }
        }
    }

    // ---- HFMA2 main loop: 32 anchors x 28 dims x 2 pixels ----
    __half2 acc[AG];
#pragma unroll
    for (int a = 0; a < AG; a++) acc[a] = __half2half2(__float2half(0.0f));

#pragma unroll
    for (int a = 0; a < AG; a++) {
#pragma unroll
        for (int dq = 0; dq < DP / 4; dq++) {
            uint4 w = *reinterpret_cast<const uint4*>(&sA[a * DP + dq * 4]);
            __half2 w0 = *reinterpret_cast<__half2*>(&w.x);
            __half2 w1 = *reinterpret_cast<__half2*>(&w.y);
            __half2 w2 = *reinterpret_cast<__half2*>(&w.z);
            __half2 w3 = *reinterpret_cast<__half2*>(&w.w);
            acc[a] = __hfma2(*reinterpret_cast<__half2*>(&vv[dq * 4 + 0]), w0, acc[a]);
            acc[a] = __hfma2(*reinterpret_cast<__half2*>(&vv[dq * 4 + 1]), w1, acc[a]);
            acc[a] = __hfma2(*reinterpret_cast<__half2*>(&vv[dq * 4 + 2]), w2, acc[a]);
            acc[a] = __hfma2(*reinterpret_cast<__half2*>(&vv[dq * 4 + 3]), w3, acc[a]);
        }
    }

    // ---- exp + reduce to per-(anchor, chunk) partials ----
    {
        float s[AG];
#pragma unroll
        for (int a = 0; a < AG; a++) {
            float2 f = __half22float2(acc[a]);
            s[a] = ex2_approx(f.x) + ex2_approx(f.y);
#pragma unroll
            for (int off = 16; off > 0; off >>= 1)
                s[a] += __shfl_xor_sync(0xffffffffu, s[a], off);
        }
        if (lane == 0) {
#pragma unroll
            for (int a = 0; a < AG; a++) rS[a][wid] = s[a];
        }
        __syncthreads();
        if (tid < AG) {
            float t = 0.0f;
#pragma unroll
            for (int w = 0; w < TPB / 32; w++) t += rS[tid][w];
            int n = ng * AG + tid;
            g_sumPart[((size_t)b * NA + n) * PC + pc] = t;
        }
    }

    // ================= window + cross for (b, n = ng*32 + pc) =================
    int n = ng * AG + pc;
    int ai = aidx[n];
    int ay = ai >> 7, ax = ai & 127;
    int gy0 = ay - 12, gx0 = ax - 12;

    __syncthreads();   // everyone done with sRows (pixel builds) + rS read

    // Stage 25x25x3 region around anchor into sRows (clamped)
    for (int t = tid; t < 25 * 25 * 3; t += TPB) {
        int ry = t / 75;
        int rem = t - ry * 75;
        int rx = rem / 3;
        int c  = rem - rx * 3;
        int gy = iclamp(gy0 + ry, 0, HH - 1);
        int gx = iclamp(gx0 + rx, 0, WW - 1);
        sRows[t] = lat[(((size_t)(b * HH + gy) * WW + gx) * 3) + c];
    }
    __syncthreads();

    // Anchor patch from region (every thread; region center)
    float av[DP];
    {
        float ss = 0.0f;
        int d = 0;
#pragma unroll
        for (int dy = -1; dy <= 1; dy++) {
            int ry = iclamp(ay + dy, 0, HH - 1) - gy0;
#pragma unroll
            for (int dx = -1; dx <= 1; dx++) {
                int rx = iclamp(ax + dx, 0, WW - 1) - gx0;
                const float* s = &sRows[(ry * 25 + rx) * 3];
                float a0 = s[0], a1 = s[1], a2 = s[2];
                av[d] = a0; av[d + 1] = a1; av[d + 2] = a2;
                ss += a0 * a0 + a1 * a1 + a2 * a2;
                d += 3;
            }
        }
        float inv = 1.0f / fmaxf(sqrtf(ss), 1e-12f);
#pragma unroll
        for (int k = 0; k < D; k++) av[k] *= inv;
        av[D] = 0.0f;
    }

    float pos = 0.0f, in121 = 0.0f, cross = 0.0f;
    int pcnt = 0, ccnt = 0, c121 = 0;

    // 23x23 window candidates from region
    for (int t = tid; t < 23 * 23; t += TPB) {
        int dy = t / 23 - 11;
        int dx = t % 23 - 11;
        int d2 = dy * dy + dx * dx;
        int y = ay + dy, x = ax + dx;
        if (d2 <= 121 && y >= 0 && y < HH && x >= 0 && x < WW) {
            c121++;
            if (d2 > 0 && d2 <= 9) pcnt++;
            if (d2 <= 4) ccnt++;
            // build candidate patch from region
            float cv[DP];
            float ss = 0.0f;
            int d = 0;
#pragma unroll
            for (int dy2 = -1; dy2 <= 1; dy2++) {
                int ry = iclamp(y + dy2, 0, HH - 1) - gy0;
#pragma unroll
                for (int dx2 = -1; dx2 <= 1; dx2++) {
                    int rx = iclamp(x + dx2, 0, WW - 1) - gx0;
                    const float* s = &sRows[(ry * 25 + rx) * 3];
                    float a0 = s[0], a1 = s[1], a2 = s[2];
                    cv[d] = a0; cv[d + 1] = a1; cv[d + 2] = a2;
                    ss += a0 * a0 + a1 * a1 + a2 * a2;
                    d += 3;
                }
            }
            float inv = 1.0f / fmaxf(sqrtf(ss), 1e-12f);
#pragma unroll
            for (int k = 0; k < D; k++) cv[k] *= inv;
            float e = __expf(dot27(av, cv));
            in121 += e;
            if (d2 > 0 && d2 <= 9) pos += e;
        }
    }

    // cross-batch: 13 offsets (d2<=4) x other batches, from GLOBAL latents
    {
        const int ody[13] = {-2,-1,-1,-1, 0, 0, 0, 0, 0, 1, 1, 1, 2};
        const int odx[13] = { 0,-1, 0, 1,-2,-1, 0, 1, 2,-1, 0, 1, 0};
        if (tid < 13 * B) {
            int o = tid >> 3;
            int k = tid & 7;
            int y = ay + ody[o], x = ax + odx[o];
            if (k != b && y >= 0 && y < HH && x >= 0 && x < WW) {
                float cv[DP];
                build_patch_global(lat, k, y, x, cv);
                cross += __expf(2.0f * dot27(av, cv));
            }
        }
    }

    // block reduce
    __shared__ float rf[3][TPB / 32];
    __shared__ int   ri[3][TPB / 32];
#pragma unroll
    for (int off = 16; off > 0; off >>= 1) {
        pos   += __shfl_xor_sync(0xffffffffu, pos, off);
        in121 += __shfl_xor_sync(0xffffffffu, in121, off);
        cross += __shfl_xor_sync(0xffffffffu, cross, off);
        pcnt  += __shfl_xor_sync(0xffffffffu, pcnt, off);
        ccnt  += __shfl_xor_sync(0xffffffffu, ccnt, off);
        c121  += __shfl_xor_sync(0xffffffffu, c121, off);
    }
    if (lane == 0) {
        rf[0][wid] = pos; rf[1][wid] = in121; rf[2][wid] = cross;
        ri[0][wid] = pcnt; ri[1][wid] = ccnt; ri[2][wid] = c121;
    }
    __syncthreads();
    if (tid == 0) {
        float P = 0, I = 0, X = 0; int pc2 = 0, cc2 = 0, c12 = 0;
#pragma unroll
        for (int w = 0; w < TPB / 32; w++) {
            P += rf[0][w]; I += rf[1][w]; X += rf[2][w];
            pc2 += ri[0][w]; cc2 += ri[1][w]; c12 += ri[2][w];
        }
        g_pos  [(size_t)b * NA + n] = P;
        g_in121[(size_t)b * NA + n] = I;
        g_cross[(size_t)b * NA + n] = X;
        if (b == 0) {
            g_cnt[n * 3 + 0] = pc2;
            g_cnt[n * 3 + 1] = cc2;
            g_cnt[n * 3 + 2] = c12;
        }
    }
}

// ---------------------------------------------------------------------------
// Kernel 2: per-(b,n) loss + global reduce. 1 block, 1024 threads.
// ---------------------------------------------------------------------------
__global__ void __launch_bounds__(1024)
final_kernel(float* __restrict__ out)
{
    int t = threadIdx.x;       // 0..1023
    int b = t >> 7;            // 0..7
    int n = t & 127;           // 0..127

    int pcnt = g_cnt[n * 3 + 0];
    int ccnt = g_cnt[n * 3 + 1];
    int c121 = g_cnt[n * 3 + 2];
    int ncnt = NP - c121;

    const float4* sp = reinterpret_cast<const float4*>(
        g_sumPart + ((size_t)b * NA + n) * PC);
    float tsum = 0.0f;
#pragma unroll
    for (int i = 0; i < PC / 4; i++) {
        float4 q = sp[i];
        tsum += q.x + q.y + q.z + q.w;
    }

    float ps = g_pos  [(size_t)b * NA + n];
    float ns = tsum - g_in121[(size_t)b * NA + n];
    float cs = g_cross[(size_t)b * NA + n];

    float pm = (pcnt > 0) ? ps / (float)max(pcnt, 1) : 1.0f;
    float nm = ns / (float)max(ncnt, 1);
    float cm = cs / (float)max((B - 1) * ccnt, 1);
    float lw = -__logf(pm / (pm + nm + 1e-8f));
    float la = -__logf(pm / (pm + cm + 1e-8f));
    float per = (ncnt > 0 ? lw : 0.0f) + (ccnt > 0 ? la : 0.0f);

    bool valid = (pcnt > 0) && (ncnt > 0 || ccnt > 0);
    float tot = valid ? per : 0.0f;
    int   nv  = valid ? 1 : 0;

    __shared__ float sT[1024];
    __shared__ int   sV[1024];
    sT[t] = tot; sV[t] = nv;
    __syncthreads();
    for (int s = 512; s > 0; s >>= 1) {
        if (t < s) { sT[t] += sT[t + s]; sV[t] += sV[t + s]; }
        __syncthreads();
    }
    if (t == 0) out[0] = (sV[0] > 0) ? sT[0] / (float)sV[0] : 0.0f;
}

// ---------------------------------------------------------------------------
extern "C" void kernel_launch(void* const* d_in, const int* in_sizes, int n_in,
                              void* d_out, int out_size)
{
    const float* latents = (const float*)d_in[0];
    const int*   aidx    = (const int*)d_in[1];
    float*       out     = (float*)d_out;

    (void)in_sizes; (void)n_in; (void)out_size;

    dim3 g(PC, NG, B);
    mega_kernel<<<g, TPB>>>(latents, aidx);

    final_kernel<<<1, 1024>>>(out);
}

// round 16
// speedup vs baseline: 1.2586x; 1.2586x over previous
#include <cuda_runtime.h>
#include <cuda_fp16.h>
#include <math.h>
#include <stdint.h>

// Problem constants
#define B    8
#define HH   128
#define WW   128
#define NP   16384        // H*W
#define D    27           // PATCH*PATCH*C
#define DP   28           // padded
#define NA   128          // number of anchors
#define AG   16           // anchors per group (main kernel)
#define NG   (NA / AG)    // 8 anchor groups
#define PC   16           // p-chunks
#define PCHUNK (NP / PC)  // 1024 pixels per chunk
#define TPB  256
#define LOG2E 1.4426950408889634f

// Scratch (device globals)
__device__ __align__(16) float  g_pn[B * NP * DP];   // [b][p][d] fp32 (window/cross/anchors)
__device__ __align__(16) __half g_ph[B * DP * NP];   // [b][d][p] fp16 d-major (main kernel)
__device__ __align__(16) float  g_sumPart[B * NA * PC];
__device__ float g_pos  [B * NA];
__device__ float g_in121[B * NA];
__device__ float g_cross[B * NA];
__device__ int   g_cnt  [NA * 3];

__device__ __forceinline__ float ex2_approx(float x) {
    float y;
    asm("ex2.approx.f32 %0, %1;" : "=f"(y) : "f"(x));
    return y;
}

__device__ __forceinline__ int iclamp(int v, int lo, int hi) {
    return min(max(v, lo), hi);
}

__device__ __forceinline__ float dot_pn(const float4* __restrict__ av,
                                        const float* __restrict__ pk)
{
    const float4* q = reinterpret_cast<const float4*>(pk);
    float dot = 0.0f;
#pragma unroll
    for (int k = 0; k < DP / 4; k++) {
        float4 a = av[k], p = q[k];
        dot = fmaf(a.x, p.x, fmaf(a.y, p.y, fmaf(a.z, p.z, fmaf(a.w, p.w, dot))));
    }
    return dot;
}

// ---------------------------------------------------------------------------
// Kernel 1: normalized patches via smem row staging.
// Block = 2 image rows of one batch (256 pixels). Stage rows r-1..r+2 (6KB)
// coalesced, build patches from smem -> g_pn (fp32 p-major) + g_ph (fp16 d-major).
// grid = B * HH/2 = 512 blocks.
// ---------------------------------------------------------------------------
__global__ void __launch_bounds__(TPB)
patch_kernel(const float* __restrict__ lat)
{
    __shared__ float sRows[4 * WW * 3];   // 1536 floats = 6 KB

    int blk = blockIdx.x;
    int b  = blk >> 6;            // 0..7
    int r0 = (blk & 63) * 2;      // first of 2 rows
    int tid = threadIdx.x;

    // Stage rows r0-1 .. r0+2 (clamped), fully coalesced
    int rm1 = r0 - 1;
    for (int t = tid; t < 4 * WW * 3; t += TPB) {
        int s = t / (WW * 3);
        int j = t - s * (WW * 3);
        int gr = iclamp(rm1 + s, 0, HH - 1);
        sRows[t] = lat[((size_t)(b * HH + gr) * WW) * 3 + j];
    }
    __syncthreads();

    int y = r0 + (tid >> 7);      // this thread's row
    int x = tid & 127;
    int p = (y << 7) | x;

    float v[DP];
    float ss = 0.0f;
    int d = 0;
#pragma unroll
    for (int dy = -1; dy <= 1; dy++) {
        int ys = iclamp(y + dy, 0, HH - 1) - rm1;   // slot 0..3
#pragma unroll
        for (int dx = -1; dx <= 1; dx++) {
            int xs = iclamp(x + dx, 0, WW - 1);
            const float* s = &sRows[(ys * WW + xs) * 3];
            float a0 = s[0], a1 = s[1], a2 = s[2];
            v[d] = a0; v[d + 1] = a1; v[d + 2] = a2;
            ss += a0 * a0 + a1 * a1 + a2 * a2;
            d += 3;
        }
    }
    float inv = 1.0f / fmaxf(sqrtf(ss), 1e-12f);
#pragma unroll
    for (int k = 0; k < D; k++) v[k] *= inv;
    v[D] = 0.0f;

    // fp32 p-major copy (7 x float4)
    float4* dstP = reinterpret_cast<float4*>(g_pn + ((size_t)b * NP + p) * DP);
#pragma unroll
    for (int k = 0; k < DP / 4; k++)
        dstP[k] = make_float4(v[4 * k], v[4 * k + 1], v[4 * k + 2], v[4 * k + 3]);

    // fp16 d-major copy (2B stores, coalesced across p per d)
    __half* dstH = g_ph + (size_t)b * DP * NP + p;
#pragma unroll
    for (int k = 0; k < DP; k++)
        dstH[(size_t)k * NP] = __float2half(v[k]);
}

// ---------------------------------------------------------------------------
// Kernel 2: UNMASKED total exp-sums via HFMA2 (2 fp16 MACs per issue slot).
// grid (PC, NG, B), block 256. Each thread: 4 pixels x 16 anchors.
// ---------------------------------------------------------------------------
__global__ void __launch_bounds__(TPB, 2)
main_kernel(const int* __restrict__ aidx)
{
    int pc = blockIdx.x;
    int nt = blockIdx.y;
    int b  = blockIdx.z;
    int tid = threadIdx.x;

    __shared__ unsigned int sA[AG * DP];   // duplicated half2 (a_d, a_d)
    __shared__ float rS[AG][TPB / 32];

    for (int t = tid; t < AG * DP; t += TPB) {
        int a = t / DP, dd = t % DP;
        float w = 0.0f;
        if (dd < D)
            w = g_pn[((size_t)b * NP + aidx[nt * AG + a]) * DP + dd] * LOG2E;
        __half2 hh = __half2half2(__float2half(w));
        sA[t] = *reinterpret_cast<unsigned int*>(&hh);
    }
    __syncthreads();

    const __half* pb = g_ph + (size_t)b * DP * NP;
    int p0 = pc * PCHUNK + tid * 4;

    __half2 acc[AG][2];
#pragma unroll
    for (int a = 0; a < AG; a++) {
        acc[a][0] = __half2half2(__float2half(0.0f));
        acc[a][1] = acc[a][0];
    }

#pragma unroll
    for (int dq = 0; dq < DP / 4; dq++) {
        __half2 v[4][2];
#pragma unroll
        for (int j = 0; j < 4; j++) {
            uint2 raw = *reinterpret_cast<const uint2*>(pb + (size_t)(dq * 4 + j) * NP + p0);
            v[j][0] = *reinterpret_cast<__half2*>(&raw.x);
            v[j][1] = *reinterpret_cast<__half2*>(&raw.y);
        }
#pragma unroll
        for (int a = 0; a < AG; a++) {
            uint4 w = *reinterpret_cast<const uint4*>(&sA[a * DP + dq * 4]);
            __half2 w0 = *reinterpret_cast<__half2*>(&w.x);
            __half2 w1 = *reinterpret_cast<__half2*>(&w.y);
            __half2 w2 = *reinterpret_cast<__half2*>(&w.z);
            __half2 w3 = *reinterpret_cast<__half2*>(&w.w);
            acc[a][0] = __hfma2(v[0][0], w0, acc[a][0]);
            acc[a][1] = __hfma2(v[0][1], w0, acc[a][1]);
            acc[a][0] = __hfma2(v[1][0], w1, acc[a][0]);
            acc[a][1] = __hfma2(v[1][1], w1, acc[a][1]);
            acc[a][0] = __hfma2(v[2][0], w2, acc[a][0]);
            acc[a][1] = __hfma2(v[2][1], w2, acc[a][1]);
            acc[a][0] = __hfma2(v[3][0], w3, acc[a][0]);
            acc[a][1] = __hfma2(v[3][1], w3, acc[a][1]);
        }
    }

    float s[AG];
#pragma unroll
    for (int a = 0; a < AG; a++) {
        float2 f0 = __half22float2(acc[a][0]);
        float2 f1 = __half22float2(acc[a][1]);
        s[a] = ex2_approx(f0.x) + ex2_approx(f0.y)
             + ex2_approx(f1.x) + ex2_approx(f1.y);
#pragma unroll
        for (int off = 16; off > 0; off >>= 1)
            s[a] += __shfl_xor_sync(0xffffffffu, s[a], off);
    }

    int wid = tid >> 5, lane = tid & 31;
    if (lane == 0) {
#pragma unroll
        for (int a = 0; a < AG; a++) rS[a][wid] = s[a];
    }
    __syncthreads();

    if (tid < AG) {
        float t = 0.0f;
#pragma unroll
        for (int w = 0; w < TPB / 32; w++) t += rS[tid][w];
        int n = nt * AG + tid;
        g_sumPart[((size_t)b * NA + n) * PC + pc] = t;
    }
}

// ---------------------------------------------------------------------------
// Kernel 3: window terms (pos, in121, counts) + cross-batch term. All fp32.
// grid (NA, B), block 128.
// ---------------------------------------------------------------------------
__global__ void window_kernel(const int* __restrict__ aidx)
{
    int n = blockIdx.x;
    int b = blockIdx.y;
    int tid = threadIdx.x;

    int ai = aidx[n];
    float4 av[DP / 4];
    {
        const float4* src = reinterpret_cast<const float4*>(
            g_pn + ((size_t)b * NP + ai) * DP);
#pragma unroll
        for (int k = 0; k < DP / 4; k++) av[k] = src[k];
    }

    int ay = ai >> 7, ax = ai & 127;

    float pos = 0.0f, in121 = 0.0f, cross = 0.0f;
    int pcnt = 0, ccnt = 0, c121 = 0;

    for (int t = tid; t < 23 * 23; t += 128) {
        int dy = t / 23 - 11;
        int dx = t % 23 - 11;
        int d2 = dy * dy + dx * dx;
        int y = ay + dy, x = ax + dx;
        if (d2 <= 121 && y >= 0 && y < HH && x >= 0 && x < WW) {
            c121++;
            if (d2 > 0 && d2 <= 9) pcnt++;
            if (d2 <= 4) ccnt++;
            int p = (y << 7) | x;
            float dot = dot_pn(av, g_pn + ((size_t)b * NP + p) * DP);
            float e = __expf(dot);
            in121 += e;
            if (d2 > 0 && d2 <= 9) pos += e;
        }
    }

    {
        const int ody[13] = {-2,-1,-1,-1, 0, 0, 0, 0, 0, 1, 1, 1, 2};
        const int odx[13] = { 0,-1, 0, 1,-2,-1, 0, 1, 2,-1, 0, 1, 0};
        if (tid < 13 * B) {
            int o = tid >> 3;
            int k = tid & 7;
            int y = ay + ody[o], x = ax + odx[o];
            if (k != b && y >= 0 && y < HH && x >= 0 && x < WW) {
                int p = (y << 7) | x;
                float dot = dot_pn(av, g_pn + ((size_t)k * NP + p) * DP);
                cross += __expf(2.0f * dot);
            }
        }
    }

    __shared__ float rf[3][4];
    __shared__ int   ri[3][4];
#pragma unroll
    for (int off = 16; off > 0; off >>= 1) {
        pos   += __shfl_xor_sync(0xffffffffu, pos, off);
        in121 += __shfl_xor_sync(0xffffffffu, in121, off);
        cross += __shfl_xor_sync(0xffffffffu, cross, off);
        pcnt  += __shfl_xor_sync(0xffffffffu, pcnt, off);
        ccnt  += __shfl_xor_sync(0xffffffffu, ccnt, off);
        c121  += __shfl_xor_sync(0xffffffffu, c121, off);
    }
    int wid = tid >> 5, lane = tid & 31;
    if (lane == 0) {
        rf[0][wid] = pos; rf[1][wid] = in121; rf[2][wid] = cross;
        ri[0][wid] = pcnt; ri[1][wid] = ccnt; ri[2][wid] = c121;
    }
    __syncthreads();
    if (tid == 0) {
        float P = 0, I = 0, X = 0; int pc2 = 0, cc2 = 0, c12 = 0;
#pragma unroll
        for (int w = 0; w < 4; w++) {
            P += rf[0][w]; I += rf[1][w]; X += rf[2][w];
            pc2 += ri[0][w]; cc2 += ri[1][w]; c12 += ri[2][w];
        }
        g_pos  [(size_t)b * NA + n] = P;
        g_in121[(size_t)b * NA + n] = I;
        g_cross[(size_t)b * NA + n] = X;
        if (b == 0) {
            g_cnt[n * 3 + 0] = pc2;
            g_cnt[n * 3 + 1] = cc2;
            g_cnt[n * 3 + 2] = c12;
        }
    }
}

// ---------------------------------------------------------------------------
// Kernel 4: per-(b,n) loss + global reduce. 1 block, 1024 threads.
// ---------------------------------------------------------------------------
__global__ void __launch_bounds__(1024)
final_kernel(float* __restrict__ out)
{
    int t = threadIdx.x;       // 0..1023
    int b = t >> 7;            // 0..7
    int n = t & 127;           // 0..127

    int pcnt = g_cnt[n * 3 + 0];
    int ccnt = g_cnt[n * 3 + 1];
    int c121 = g_cnt[n * 3 + 2];
    int ncnt = NP - c121;

    const float4* sp = reinterpret_cast<const float4*>(
        g_sumPart + ((size_t)b * NA + n) * PC);
    float tsum = 0.0f;
#pragma unroll
    for (int i = 0; i < PC / 4; i++) {
        float4 q = sp[i];
        tsum += q.x + q.y + q.z + q.w;
    }

    float ps = g_pos  [(size_t)b * NA + n];
    float ns = tsum - g_in121[(size_t)b * NA + n];
    float cs = g_cross[(size_t)b * NA + n];

    float pm = (pcnt > 0) ? ps / (float)max(pcnt, 1) : 1.0f;
    float nm = ns / (float)max(ncnt, 1);
    float cm = cs / (float)max((B - 1) * ccnt, 1);
    float lw = -__logf(pm / (pm + nm + 1e-8f));
    float la = -__logf(pm / (pm + cm + 1e-8f));
    float per = (ncnt > 0 ? lw : 0.0f) + (ccnt > 0 ? la : 0.0f);

    bool valid = (pcnt > 0) && (ncnt > 0 || ccnt > 0);
    float tot = valid ? per : 0.0f;
    int   nv  = valid ? 1 : 0;

    __shared__ float sT[1024];
    __shared__ int   sV[1024];
    sT[t] = tot; sV[t] = nv;
    __syncthreads();
    for (int s = 512; s > 0; s >>= 1) {
        if (t < s) { sT[t] += sT[t + s]; sV[t] += sV[t + s]; }
        __syncthreads();
    }
    if (t == 0) out[0] = (sV[0] > 0) ? sT[0] / (float)sV[0] : 0.0f;
}

// ---------------------------------------------------------------------------
extern "C" void kernel_launch(void* const* d_in, const int* in_sizes, int n_in,
                              void* d_out, int out_size)
{
    const float* latents = (const float*)d_in[0];
    const int*   aidx    = (const int*)d_in[1];
    float*       out     = (float*)d_out;

    (void)in_sizes; (void)n_in; (void)out_size;

    patch_kernel<<<B * HH / 2, TPB>>>(latents);

    dim3 g2(PC, NG, B);
    main_kernel<<<g2, TPB>>>(aidx);

    dim3 g3(NA, B);
    window_kernel<<<g3, 128>>>(aidx);

    final_kernel<<<1, 1024>>>(out);
}

// round 17
// speedup vs baseline: 1.2649x; 1.0050x over previous
#include <cuda_runtime.h>
#include <cuda_fp16.h>
#include <math.h>
#include <stdint.h>

// Problem constants
#define B    8
#define HH   128
#define WW   128
#define NP   16384        // H*W
#define D    27           // PATCH*PATCH*C
#define DP   28           // padded
#define NA   128          // number of anchors
#define AG   16           // anchors per group (main kernel)
#define NG   (NA / AG)    // 8 anchor groups
#define PC   16           // p-chunks
#define PCHUNK (NP / PC)  // 1024 pixels per chunk
#define TPB  256
#define LOG2E 1.4426950408889634f

// Scratch (device globals)
__device__ __align__(16) float  g_pn[B * NP * DP];   // [b][p][d] fp32 (window/cross/anchors)
__device__ __align__(16) __half g_ph[B * DP * NP];   // [b][d][p] fp16 d-major (main kernel)
__device__ __align__(16) float  g_sumPart[B * NA * PC];
__device__ float g_pos  [B * NA];
__device__ float g_in121[B * NA];
__device__ float g_cross[B * NA];
__device__ int   g_cnt  [NA * 3];

__device__ __forceinline__ float ex2_approx(float x) {
    float y;
    asm("ex2.approx.f32 %0, %1;" : "=f"(y) : "f"(x));
    return y;
}

__device__ __forceinline__ int iclamp(int v, int lo, int hi) {
    return min(max(v, lo), hi);
}

__device__ __forceinline__ float dot_pn(const float4* __restrict__ av,
                                        const float* __restrict__ pk)
{
    const float4* q = reinterpret_cast<const float4*>(pk);
    float dot = 0.0f;
#pragma unroll
    for (int k = 0; k < DP / 4; k++) {
        float4 a = av[k], p = q[k];
        dot = fmaf(a.x, p.x, fmaf(a.y, p.y, fmaf(a.z, p.z, fmaf(a.w, p.w, dot))));
    }
    return dot;
}

// ---------------------------------------------------------------------------
// Kernel 1: normalized patches via smem row staging.
// Block = 2 image rows of one batch (256 pixels). grid = B*HH/2 = 512.
// ---------------------------------------------------------------------------
__global__ void __launch_bounds__(TPB)
patch_kernel(const float* __restrict__ lat)
{
    __shared__ float sRows[4 * WW * 3];   // 6 KB

    int blk = blockIdx.x;
    int b  = blk >> 6;            // 0..7
    int r0 = (blk & 63) * 2;      // first of 2 rows
    int tid = threadIdx.x;

    int rm1 = r0 - 1;
    for (int t = tid; t < 4 * WW * 3; t += TPB) {
        int s = t / (WW * 3);
        int j = t - s * (WW * 3);
        int gr = iclamp(rm1 + s, 0, HH - 1);
        sRows[t] = lat[((size_t)(b * HH + gr) * WW) * 3 + j];
    }
    __syncthreads();

    int y = r0 + (tid >> 7);
    int x = tid & 127;
    int p = (y << 7) | x;

    float v[DP];
    float ss = 0.0f;
    int d = 0;
#pragma unroll
    for (int dy = -1; dy <= 1; dy++) {
        int ys = iclamp(y + dy, 0, HH - 1) - rm1;
#pragma unroll
        for (int dx = -1; dx <= 1; dx++) {
            int xs = iclamp(x + dx, 0, WW - 1);
            const float* s = &sRows[(ys * WW + xs) * 3];
            float a0 = s[0], a1 = s[1], a2 = s[2];
            v[d] = a0; v[d + 1] = a1; v[d + 2] = a2;
            ss += a0 * a0 + a1 * a1 + a2 * a2;
            d += 3;
        }
    }
    float inv = 1.0f / fmaxf(sqrtf(ss), 1e-12f);
#pragma unroll
    for (int k = 0; k < D; k++) v[k] *= inv;
    v[D] = 0.0f;

    float4* dstP = reinterpret_cast<float4*>(g_pn + ((size_t)b * NP + p) * DP);
#pragma unroll
    for (int k = 0; k < DP / 4; k++)
        dstP[k] = make_float4(v[4 * k], v[4 * k + 1], v[4 * k + 2], v[4 * k + 3]);

    __half* dstH = g_ph + (size_t)b * DP * NP + p;
#pragma unroll
    for (int k = 0; k < DP; k++)
        dstH[(size_t)k * NP] = __float2half(v[k]);
}

// ---------------------------------------------------------------------------
// Kernel 2: UNMASKED total exp-sums via HFMA2.
// grid (PC, NG, B), block 256, 3 CTAs/SM (occupancy experiment).
// ---------------------------------------------------------------------------
__global__ void __launch_bounds__(TPB, 3)
main_kernel(const int* __restrict__ aidx)
{
    int pc = blockIdx.x;
    int nt = blockIdx.y;
    int b  = blockIdx.z;
    int tid = threadIdx.x;

    __shared__ unsigned int sA[AG * DP];   // duplicated half2 (a_d, a_d)
    __shared__ float rS[AG][TPB / 32];

    for (int t = tid; t < AG * DP; t += TPB) {
        int a = t / DP, dd = t % DP;
        float w = 0.0f;
        if (dd < D)
            w = g_pn[((size_t)b * NP + aidx[nt * AG + a]) * DP + dd] * LOG2E;
        __half2 hh = __half2half2(__float2half(w));
        sA[t] = *reinterpret_cast<unsigned int*>(&hh);
    }
    __syncthreads();

    const __half* pb = g_ph + (size_t)b * DP * NP;
    int p0 = pc * PCHUNK + tid * 4;

    __half2 acc[AG][2];
#pragma unroll
    for (int a = 0; a < AG; a++) {
        acc[a][0] = __half2half2(__float2half(0.0f));
        acc[a][1] = acc[a][0];
    }

#pragma unroll
    for (int dq = 0; dq < DP / 4; dq++) {
        __half2 v[4][2];
#pragma unroll
        for (int j = 0; j < 4; j++) {
            uint2 raw = *reinterpret_cast<const uint2*>(pb + (size_t)(dq * 4 + j) * NP + p0);
            v[j][0] = *reinterpret_cast<__half2*>(&raw.x);
            v[j][1] = *reinterpret_cast<__half2*>(&raw.y);
        }
#pragma unroll
        for (int a = 0; a < AG; a++) {
            uint4 w = *reinterpret_cast<const uint4*>(&sA[a * DP + dq * 4]);
            __half2 w0 = *reinterpret_cast<__half2*>(&w.x);
            __half2 w1 = *reinterpret_cast<__half2*>(&w.y);
            __half2 w2 = *reinterpret_cast<__half2*>(&w.z);
            __half2 w3 = *reinterpret_cast<__half2*>(&w.w);
            acc[a][0] = __hfma2(v[0][0], w0, acc[a][0]);
            acc[a][1] = __hfma2(v[0][1], w0, acc[a][1]);
            acc[a][0] = __hfma2(v[1][0], w1, acc[a][0]);
            acc[a][1] = __hfma2(v[1][1], w1, acc[a][1]);
            acc[a][0] = __hfma2(v[2][0], w2, acc[a][0]);
            acc[a][1] = __hfma2(v[2][1], w2, acc[a][1]);
            acc[a][0] = __hfma2(v[3][0], w3, acc[a][0]);
            acc[a][1] = __hfma2(v[3][1], w3, acc[a][1]);
        }
    }

    float s[AG];
#pragma unroll
    for (int a = 0; a < AG; a++) {
        float2 f0 = __half22float2(acc[a][0]);
        float2 f1 = __half22float2(acc[a][1]);
        s[a] = ex2_approx(f0.x) + ex2_approx(f0.y)
             + ex2_approx(f1.x) + ex2_approx(f1.y);
#pragma unroll
        for (int off = 16; off > 0; off >>= 1)
            s[a] += __shfl_xor_sync(0xffffffffu, s[a], off);
    }

    int wid = tid >> 5, lane = tid & 31;
    if (lane == 0) {
#pragma unroll
        for (int a = 0; a < AG; a++) rS[a][wid] = s[a];
    }
    __syncthreads();

    if (tid < AG) {
        float t = 0.0f;
#pragma unroll
        for (int w = 0; w < TPB / 32; w++) t += rS[tid][w];
        int n = nt * AG + tid;
        g_sumPart[((size_t)b * NA + n) * PC + pc] = t;
    }
}

// ---------------------------------------------------------------------------
// Kernel 3: window terms (pos, in121, counts) + cross-batch term. All fp32.
// grid (NA, B), block 128.
// ---------------------------------------------------------------------------
__global__ void window_kernel(const int* __restrict__ aidx)
{
    int n = blockIdx.x;
    int b = blockIdx.y;
    int tid = threadIdx.x;

    int ai = aidx[n];
    float4 av[DP / 4];
    {
        const float4* src = reinterpret_cast<const float4*>(
            g_pn + ((size_t)b * NP + ai) * DP);
#pragma unroll
        for (int k = 0; k < DP / 4; k++) av[k] = src[k];
    }

    int ay = ai >> 7, ax = ai & 127;

    float pos = 0.0f, in121 = 0.0f, cross = 0.0f;
    int pcnt = 0, ccnt = 0, c121 = 0;

    for (int t = tid; t < 23 * 23; t += 128) {
        int dy = t / 23 - 11;
        int dx = t % 23 - 11;
        int d2 = dy * dy + dx * dx;
        int y = ay + dy, x = ax + dx;
        if (d2 <= 121 && y >= 0 && y < HH && x >= 0 && x < WW) {
            c121++;
            if (d2 > 0 && d2 <= 9) pcnt++;
            if (d2 <= 4) ccnt++;
            int p = (y << 7) | x;
            float dot = dot_pn(av, g_pn + ((size_t)b * NP + p) * DP);
            float e = __expf(dot);
            in121 += e;
            if (d2 > 0 && d2 <= 9) pos += e;
        }
    }

    {
        const int ody[13] = {-2,-1,-1,-1, 0, 0, 0, 0, 0, 1, 1, 1, 2};
        const int odx[13] = { 0,-1, 0, 1,-2,-1, 0, 1, 2,-1, 0, 1, 0};
        if (tid < 13 * B) {
            int o = tid >> 3;
            int k = tid & 7;
            int y = ay + ody[o], x = ax + odx[o];
            if (k != b && y >= 0 && y < HH && x >= 0 && x < WW) {
                int p = (y << 7) | x;
                float dot = dot_pn(av, g_pn + ((size_t)k * NP + p) * DP);
                cross += __expf(2.0f * dot);
            }
        }
    }

    __shared__ float rf[3][4];
    __shared__ int   ri[3][4];
#pragma unroll
    for (int off = 16; off > 0; off >>= 1) {
        pos   += __shfl_xor_sync(0xffffffffu, pos, off);
        in121 += __shfl_xor_sync(0xffffffffu, in121, off);
        cross += __shfl_xor_sync(0xffffffffu, cross, off);
        pcnt  += __shfl_xor_sync(0xffffffffu, pcnt, off);
        ccnt  += __shfl_xor_sync(0xffffffffu, ccnt, off);
        c121  += __shfl_xor_sync(0xffffffffu, c121, off);
    }
    int wid = tid >> 5, lane = tid & 31;
    if (lane == 0) {
        rf[0][wid] = pos; rf[1][wid] = in121; rf[2][wid] = cross;
        ri[0][wid] = pcnt; ri[1][wid] = ccnt; ri[2][wid] = c121;
    }
    __syncthreads();
    if (tid == 0) {
        float P = 0, I = 0, X = 0; int pc2 = 0, cc2 = 0, c12 = 0;
#pragma unroll
        for (int w = 0; w < 4; w++) {
            P += rf[0][w]; I += rf[1][w]; X += rf[2][w];
            pc2 += ri[0][w]; cc2 += ri[1][w]; c12 += ri[2][w];
        }
        g_pos  [(size_t)b * NA + n] = P;
        g_in121[(size_t)b * NA + n] = I;
        g_cross[(size_t)b * NA + n] = X;
        if (b == 0) {
            g_cnt[n * 3 + 0] = pc2;
            g_cnt[n * 3 + 1] = cc2;
            g_cnt[n * 3 + 2] = c12;
        }
    }
}

// ---------------------------------------------------------------------------
// Kernel 4: per-(b,n) loss + global reduce. 1 block, 1024 threads.
// ---------------------------------------------------------------------------
__global__ void __launch_bounds__(1024)
final_kernel(float* __restrict__ out)
{
    int t = threadIdx.x;       // 0..1023
    int b = t >> 7;            // 0..7
    int n = t & 127;           // 0..127

    int pcnt = g_cnt[n * 3 + 0];
    int ccnt = g_cnt[n * 3 + 1];
    int c121 = g_cnt[n * 3 + 2];
    int ncnt = NP - c121;

    const float4* sp = reinterpret_cast<const float4*>(
        g_sumPart + ((size_t)b * NA + n) * PC);
    float tsum = 0.0f;
#pragma unroll
    for (int i = 0; i < PC / 4; i++) {
        float4 q = sp[i];
        tsum += q.x + q.y + q.z + q.w;
    }

    float ps = g_pos  [(size_t)b * NA + n];
    float ns = tsum - g_in121[(size_t)b * NA + n];
    float cs = g_cross[(size_t)b * NA + n];

    float pm = (pcnt > 0) ? ps / (float)max(pcnt, 1) : 1.0f;
    float nm = ns / (float)max(ncnt, 1);
    float cm = cs / (float)max((B - 1) * ccnt, 1);
    float lw = -__logf(pm / (pm + nm + 1e-8f));
    float la = -__logf(pm / (pm + cm + 1e-8f));
    float per = (ncnt > 0 ? lw : 0.0f) + (ccnt > 0 ? la : 0.0f);

    bool valid = (pcnt > 0) && (ncnt > 0 || ccnt > 0);
    float tot = valid ? per : 0.0f;
    int   nv  = valid ? 1 : 0;

    __shared__ float sT[1024];
    __shared__ int   sV[1024];
    sT[t] = tot; sV[t] = nv;
    __syncthreads();
    for (int s = 512; s > 0; s >>= 1) {
        if (t < s) { sT[t] += sT[t + s]; sV[t] += sV[t + s]; }
        __syncthreads();
    }
    if (t == 0) out[0] = (sV[0] > 0) ? sT[0] / (float)sV[0] : 0.0f;
}

// ---------------------------------------------------------------------------
extern "C" void kernel_launch(void* const* d_in, const int* in_sizes, int n_in,
                              void* d_out, int out_size)
{
    const float* latents = (const float*)d_in[0];
    const int*   aidx    = (const int*)d_in[1];
    float*       out     = (float*)d_out;

    (void)in_sizes; (void)n_in; (void)out_size;

    patch_kernel<<<B * HH / 2, TPB>>>(latents);

    dim3 g2(PC, NG, B);
    main_kernel<<<g2, TPB>>>(aidx);

    dim3 g3(NA, B);
    window_kernel<<<g3, 128>>>(aidx);

    final_kernel<<<1, 1024>>>(out);
}